// round 16
// baseline (speedup 1.0000x reference)
#include <cuda_runtime.h>
#include <mma.h>
#include <cuda_bf16.h>
#include <cstdint>
#include <cstdio>

using namespace nvcuda;

#define L_SEQ 256
#define HID 768

// ---------------- scratch ----------------
__device__ float g_X[8192u * 512];            // embedded input (tf32-rounded), row m = t*32+b
__device__ float g_xp[2u * 256 * 768 * 32];   // xp[d][t][j][b]
__device__ __nv_bfloat16 g_hH[2][2][768][32]; // ping-pong h hi [pp][d][k][b] (k-major)
__device__ __nv_bfloat16 g_hL[2][2][768][32]; // ping-pong h lo
__device__ float g_hcat[256u * 1536 * 32];    // layer output [t][c][b]
__device__ float g_hmat[8192u * 1536];        // [m][c] GEMM layout (tf32-rounded)
__device__ __nv_bfloat16 g_WpH[10240u * 1536];  // projection weights hi (padded)
__device__ __nv_bfloat16 g_WpL[10240u * 1536];  // projection weights lo
__device__ __nv_bfloat16 g_hmH[8192u * 1536];   // normalized input hi
__device__ __nv_bfloat16 g_hmL[8192u * 1536];   // normalized input lo
__device__ float g_wih0[2u * 768 * 512];      // rounded w_ih_l0
__device__ float g_wih1[2u * 768 * 1536];     // rounded w_ih_l1
__device__ float g_probe[128u * 10240];       // probe scratch
__device__ float g_mean[256];
__device__ float g_rstd[256];
__device__ unsigned g_flag[2][48 * 32];       // per-block step flags, 128B stride

// ---------------- helpers ----------------
__device__ __forceinline__ float tf32r(float x) {
    float r;
    asm("cvt.rna.tf32.f32 %0, %1;" : "=f"(r) : "f"(x));
    return r;
}
__device__ __forceinline__ void cp_async16(void* sdst, const void* gsrc) {
    uint32_t sa = (uint32_t)__cvta_generic_to_shared(sdst);
    asm volatile("cp.async.cg.shared.global [%0], [%1], 16;\n" :: "r"(sa), "l"(gsrc));
}
__device__ __forceinline__ void cp_commit() { asm volatile("cp.async.commit_group;\n"); }
template<int N> __device__ __forceinline__ void cp_wait() {
    asm volatile("cp.async.wait_group %0;\n" :: "n"(N));
}
__device__ __forceinline__ unsigned ld_acq(const unsigned* p) {
    unsigned o;
    asm volatile("ld.acquire.gpu.global.u32 %0, [%1];" : "=r"(o) : "l"(p) : "memory");
    return o;
}
__device__ __forceinline__ void st_rel(unsigned* p, unsigned v) {
    asm volatile("st.release.gpu.global.u32 [%0], %1;" :: "l"(p), "r"(v) : "memory");
}
__device__ __forceinline__ void bfsplit(float v, __nv_bfloat16& hi, __nv_bfloat16& lo) {
    hi = __float2bfloat16(v);
    lo = __float2bfloat16(v - __bfloat162float(hi));
}

// ---------------- embedding gather (tf32-rounded) ----------------
__global__ void embed_kernel(const int* __restrict__ tokens,
                             const float* __restrict__ emb,
                             float* __restrict__ X)
{
    int m = blockIdx.x, t = m >> 5, b = m & 31;
    int tok = tokens[b * L_SEQ + t];
    float4 v = ((const float4*)(emb + (size_t)tok * 512))[threadIdx.x];
    v.x = tf32r(v.x); v.y = tf32r(v.y); v.z = tf32r(v.z); v.w = tf32r(v.w);
    ((float4*)(X + (size_t)m * 512))[threadIdx.x] = v;
}

// ---------------- weight prep ----------------
__global__ void prep_round(const float* __restrict__ src, float* __restrict__ dst, int n4)
{
    int i = blockIdx.x * 256 + threadIdx.x;
    if (i < n4) {
        float4 v = ((const float4*)src)[i];
        v.x = tf32r(v.x); v.y = tf32r(v.y); v.z = tf32r(v.z); v.w = tf32r(v.w);
        ((float4*)dst)[i] = v;
    }
}
__global__ void prep_wsplit(const float* __restrict__ lw,
                            __nv_bfloat16* __restrict__ dh, __nv_bfloat16* __restrict__ dl)
{
    size_t i = (size_t)blockIdx.x * 256 + threadIdx.x;   // float4 idx, total 10240*384
    int row = (int)(i / 384);
    float4 v = make_float4(0.f, 0.f, 0.f, 0.f);
    if (row < 10000) v = ((const float4*)lw)[i];
    __nv_bfloat16 h0, l0, h1, l1, h2, l2, h3, l3;
    bfsplit(v.x, h0, l0); bfsplit(v.y, h1, l1); bfsplit(v.z, h2, l2); bfsplit(v.w, h3, l3);
    dh[i * 4 + 0] = h0; dh[i * 4 + 1] = h1; dh[i * 4 + 2] = h2; dh[i * 4 + 3] = h3;
    dl[i * 4 + 0] = l0; dl[i * 4 + 1] = l1; dl[i * 4 + 2] = l2; dl[i * 4 + 3] = l3;
}

// ---------------- reset for persistent recurrence ----------------
__global__ void rnn_reset()
{
    int i = blockIdx.x * blockDim.x + threadIdx.x;   // 49152 threads
    __nv_bfloat16* hH0 = &g_hH[0][0][0][0];
    __nv_bfloat16* hL0 = &g_hL[0][0][0][0];
    hH0[i] = __float2bfloat16(0.f);
    hL0[i] = __float2bfloat16(0.f);
    if (i < 2 * 48 * 32) (&g_flag[0][0])[i] = 0u;
}

// ================= GEMM (tf32, input GEMMs only) =====================
#define GBM 128
#define GBN 128
#define GBK 32
#define GLD 40
#define STGF 10240

__global__ __launch_bounds__(256, 2) void gemm2(
    const float* __restrict__ A, const float* __restrict__ W,
    const float* __restrict__ b1, const float* __restrict__ b2,
    float* __restrict__ C, int K,
    size_t wStride, size_t cStride, int bStride)
{
    extern __shared__ float sm[];
    int z = blockIdx.z;
    W  += (size_t)z * wStride;
    C  += (size_t)z * cStride;
    b1 += z * bStride;
    b2 += z * bStride;

    int tid = threadIdx.x, warp = tid >> 5, lane = tid & 31;
    int wm = warp >> 2, wn = warp & 3;
    int m0 = blockIdx.y * GBM, n0 = blockIdx.x * GBN;
    int ntiles = K / GBK;

    auto loadtile = [&](int kt, int buf) {
        int k0 = kt * GBK;
        float* sA = sm + (size_t)buf * STGF;
        float* sB = sA + GBM * GLD;
#pragma unroll
        for (int i = 0; i < 4; i++) {
            int ch = tid + i * 256, r = ch >> 3, cg = ch & 7;
            cp_async16(&sA[r * GLD + cg * 4], A + (size_t)(m0 + r) * K + k0 + cg * 4);
        }
#pragma unroll
        for (int i = 0; i < 4; i++) {
            int ch = tid + i * 256, r = ch >> 3, cg = ch & 7;
            cp_async16(&sB[r * GLD + cg * 4], W + (size_t)(n0 + r) * K + k0 + cg * 4);
        }
    };

    wmma::fragment<wmma::accumulator, 16, 16, 8, float> acc[4][2];
#pragma unroll
    for (int i = 0; i < 4; i++)
#pragma unroll
        for (int j = 0; j < 2; j++) wmma::fill_fragment(acc[i][j], 0.0f);

    loadtile(0, 0);
    cp_commit();

    int buf = 0;
    for (int kt = 0; kt < ntiles; kt++) {
        cp_wait<0>();
        __syncthreads();
        if (kt + 1 < ntiles) { loadtile(kt + 1, buf ^ 1); cp_commit(); }

        const float* A0 = sm + (size_t)buf * STGF + wm * 64 * GLD;
        const float* B0 = sm + (size_t)buf * STGF + GBM * GLD + wn * 32 * GLD;
#pragma unroll
        for (int kk = 0; kk < 4; kk++) {
            wmma::fragment<wmma::matrix_a, 16, 16, 8, wmma::precision::tf32, wmma::row_major> af[4];
            wmma::fragment<wmma::matrix_b, 16, 16, 8, wmma::precision::tf32, wmma::col_major> bf[2];
#pragma unroll
            for (int i = 0; i < 4; i++)
                wmma::load_matrix_sync(af[i], A0 + (size_t)i * 16 * GLD + kk * 8, GLD);
#pragma unroll
            for (int j = 0; j < 2; j++)
                wmma::load_matrix_sync(bf[j], B0 + (size_t)j * 16 * GLD + kk * 8, GLD);
#pragma unroll
            for (int i = 0; i < 4; i++)
#pragma unroll
                for (int j = 0; j < 2; j++)
                    wmma::mma_sync(acc[i][j], af[i], bf[j], acc[i][j]);
        }
        __syncthreads();
        buf ^= 1;
    }

    float* sC = sm + (size_t)warp * 64 * GLD;
#pragma unroll
    for (int i = 0; i < 4; i++)
#pragma unroll
        for (int j = 0; j < 2; j++)
            wmma::store_matrix_sync(sC + (size_t)i * 16 * GLD + j * 16, acc[i][j], GLD,
                                    wmma::mem_row_major);
    __syncwarp();

#pragma unroll
    for (int half = 0; half < 2; half++) {
        int ml = half * 32 + lane;
        int m = m0 + wm * 64 + ml;
        int t = m >> 5, b = m & 31;
#pragma unroll 4
        for (int nl = 0; nl < 32; nl++) {
            int n = n0 + wn * 32 + nl;
            float v = sC[ml * GLD + nl] + b1[n] + b2[n];
            C[((size_t)t * HID + n) * 32 + b] = v;
        }
    }
}

// ================= bf16 3-term GEMM v2 (projection) =============================
// 512 threads, 4x4 warp grid of 32x32 tiles over a 128x128 CTA tile.
// Full register double-buffering of fragments (fits: acc 32 + frags 64 regs).
// MODE 0: out[(b*256+t)][n] + b1 (guard Nout). MODE 2: probe scratch.
#define HLD3 40            // smem ld in halfs
#define STGH 20480

template<int MODE>
__global__ __launch_bounds__(512, 1) void gemm3(
    const __nv_bfloat16* __restrict__ Ah, const __nv_bfloat16* __restrict__ Al,
    const __nv_bfloat16* __restrict__ Wh, const __nv_bfloat16* __restrict__ Wl,
    const float* __restrict__ b1, float* __restrict__ C, int K, int Nout)
{
    extern __shared__ __align__(16) char smraw[];
    __nv_bfloat16* smh = (__nv_bfloat16*)smraw;

    int tid = threadIdx.x, warp = tid >> 5, lane = tid & 31;
    int wm = warp >> 2, wn = warp & 3;    // 4x4 grid, warp tile 32x32
    int m0 = blockIdx.y * GBM, n0 = blockIdx.x * GBN;
    int ntiles = K / GBK;

    // stage (halfs): [Ah 128*40][Al][Wh][Wl]; 512 threads -> 1 chunk/thread/array
    int lr = tid >> 2, lc = tid & 3;
    auto loadtile = [&](int kt, int buf) {
        int k0 = kt * GBK;
        __nv_bfloat16* s = smh + (size_t)buf * STGH;
        cp_async16(&s[lr * HLD3 + lc * 8],         Ah + (size_t)(m0 + lr) * K + k0 + lc * 8);
        cp_async16(&s[5120 + lr * HLD3 + lc * 8],  Al + (size_t)(m0 + lr) * K + k0 + lc * 8);
        cp_async16(&s[10240 + lr * HLD3 + lc * 8], Wh + (size_t)(n0 + lr) * K + k0 + lc * 8);
        cp_async16(&s[15360 + lr * HLD3 + lc * 8], Wl + (size_t)(n0 + lr) * K + k0 + lc * 8);
    };

    wmma::fragment<wmma::accumulator, 16, 16, 16, float> acc[2][2];
#pragma unroll
    for (int i = 0; i < 2; i++)
#pragma unroll
        for (int j = 0; j < 2; j++) wmma::fill_fragment(acc[i][j], 0.0f);

    loadtile(0, 0);
    cp_commit();

    int buf = 0;
    for (int kt = 0; kt < ntiles; kt++) {
        cp_wait<0>();
        __syncthreads();
        if (kt + 1 < ntiles) { loadtile(kt + 1, buf ^ 1); cp_commit(); }

        const __nv_bfloat16* S = smh + (size_t)buf * STGH;
        const __nv_bfloat16* A0h = S + wm * 32 * HLD3;
        const __nv_bfloat16* A0l = S + 5120 + wm * 32 * HLD3;
        const __nv_bfloat16* B0h = S + 10240 + wn * 32 * HLD3;
        const __nv_bfloat16* B0l = S + 15360 + wn * 32 * HLD3;

        // double-buffered fragments across the 2 kk sub-steps
        wmma::fragment<wmma::matrix_a, 16, 16, 16, __nv_bfloat16, wmma::row_major> ah[2][2], al[2][2];
        wmma::fragment<wmma::matrix_b, 16, 16, 16, __nv_bfloat16, wmma::col_major> bh[2][2], bl[2][2];
#pragma unroll
        for (int i = 0; i < 2; i++) {
            wmma::load_matrix_sync(ah[0][i], A0h + (size_t)i * 16 * HLD3, HLD3);
            wmma::load_matrix_sync(al[0][i], A0l + (size_t)i * 16 * HLD3, HLD3);
            wmma::load_matrix_sync(bh[0][i], B0h + (size_t)i * 16 * HLD3, HLD3);
            wmma::load_matrix_sync(bl[0][i], B0l + (size_t)i * 16 * HLD3, HLD3);
        }
#pragma unroll
        for (int kk = 0; kk < 2; kk++) {
            int cur = kk & 1, nxt = cur ^ 1;
            if (kk < 1) {
#pragma unroll
                for (int i = 0; i < 2; i++) {
                    wmma::load_matrix_sync(ah[nxt][i], A0h + (size_t)i * 16 * HLD3 + 16, HLD3);
                    wmma::load_matrix_sync(al[nxt][i], A0l + (size_t)i * 16 * HLD3 + 16, HLD3);
                    wmma::load_matrix_sync(bh[nxt][i], B0h + (size_t)i * 16 * HLD3 + 16, HLD3);
                    wmma::load_matrix_sync(bl[nxt][i], B0l + (size_t)i * 16 * HLD3 + 16, HLD3);
                }
            }
#pragma unroll
            for (int i = 0; i < 2; i++)
#pragma unroll
                for (int j = 0; j < 2; j++) {
                    wmma::mma_sync(acc[i][j], ah[cur][i], bh[cur][j], acc[i][j]);
                    wmma::mma_sync(acc[i][j], ah[cur][i], bl[cur][j], acc[i][j]);
                    wmma::mma_sync(acc[i][j], al[cur][i], bh[cur][j], acc[i][j]);
                }
        }
        buf ^= 1;
    }
    __syncthreads();   // before smem reuse for epilogue

    // epilogue: per-warp 32x40 float staging tile (16 warps * 32*40*4B = 80 KB)
    float* sC = (float*)smraw + (size_t)warp * 32 * GLD;
#pragma unroll
    for (int i = 0; i < 2; i++)
#pragma unroll
        for (int j = 0; j < 2; j++)
            wmma::store_matrix_sync(sC + (size_t)i * 16 * GLD + j * 16, acc[i][j], GLD,
                                    wmma::mem_row_major);
    __syncwarp();

    int n = n0 + wn * 32 + lane;
    if (MODE == 0) {
        if (n < Nout) {
            float bv = b1[n];
#pragma unroll 4
            for (int ml = 0; ml < 32; ml++) {
                int m = m0 + wm * 32 + ml;
                float v = sC[ml * GLD + lane] + bv;
                int row = (m & 31) * L_SEQ + (m >> 5);
                C[(size_t)row * Nout + n] = v;
            }
        }
    } else {
#pragma unroll 4
        for (int ml = 0; ml < 32; ml++) {
            int m = m0 + wm * 32 + ml;
            C[(size_t)(m & 127) * 10240 + n] = sC[ml * GLD + lane];
        }
    }
}

// ================= persistent bi-RNN layer v6 (unchanged from R15) ==============
#define SPLD 20

__global__ __launch_bounds__(512, 1) void rnn_layer(
    const float* __restrict__ xp,
    const float* __restrict__ Whh,
    float* __restrict__ hcat,
    int nsteps)
{
    extern __shared__ __align__(16) char smraw[];
    __nv_bfloat16* sWh = (__nv_bfloat16*)smraw;                 // [16][776]
    __nv_bfloat16* sWl = sWh + 16 * 776;
    float* sPart = (float*)(smraw + 2 * 16 * 776 * 2);          // [16w][2i][16r][SPLD]

    int blk = blockIdx.x;
    int d = blk / 48, jb = blk % 48, j0 = jb * 16;
    int tid = threadIdx.x, w = tid >> 5;

    const float* Wd = Whh + (size_t)d * HID * HID;
    for (int i = tid; i < 16 * 192; i += 512) {
        int j = i / 192, c = i % 192;
        float4 v = *(const float4*)&Wd[(size_t)(j0 + j) * HID + c * 4];
        float vv[4] = {v.x, v.y, v.z, v.w};
#pragma unroll
        for (int q = 0; q < 4; q++) {
            __nv_bfloat16 hi, lo;
            bfsplit(vv[q], hi, lo);
            sWh[j * 776 + c * 4 + q] = hi;
            sWl[j * 776 + c * 4 + q] = lo;
        }
    }
    __syncthreads();

    const float* xpd = xp + (size_t)d * L_SEQ * HID * 32;
    int jf = tid >> 5, bf = tid & 31;
    unsigned* flags = &g_flag[d][0];

    for (int s = 0; s < nsteps; s++) {
        int t = d ? (L_SEQ - 1 - s) : s;
        const __nv_bfloat16* hpH = &g_hH[s & 1][d][0][0];
        const __nv_bfloat16* hpL = &g_hL[s & 1][d][0][0];
        __nv_bfloat16* hnH = &g_hH[(s + 1) & 1][d][0][0];
        __nv_bfloat16* hnL = &g_hL[(s + 1) & 1][d][0][0];

        float xv = xpd[((size_t)t * HID + j0 + jf) * 32 + bf];

        wmma::fragment<wmma::accumulator, 16, 16, 16, float> acc[2];
        wmma::fill_fragment(acc[0], 0.0f);
        wmma::fill_fragment(acc[1], 0.0f);

        int kbase = w * 48;
#pragma unroll
        for (int kt = 0; kt < 3; kt++) {
            int k = kbase + kt * 16;
            wmma::fragment<wmma::matrix_a, 16, 16, 16, __nv_bfloat16, wmma::col_major> ah[2], al[2];
#pragma unroll
            for (int i = 0; i < 2; i++) {
                wmma::load_matrix_sync(ah[i], hpH + (size_t)k * 32 + i * 16, 32);
                wmma::load_matrix_sync(al[i], hpL + (size_t)k * 32 + i * 16, 32);
            }
            wmma::fragment<wmma::matrix_b, 16, 16, 16, __nv_bfloat16, wmma::col_major> bh, bl;
            wmma::load_matrix_sync(bh, sWh + k, 776);
            wmma::load_matrix_sync(bl, sWl + k, 776);
#pragma unroll
            for (int i = 0; i < 2; i++) {
                wmma::mma_sync(acc[i], ah[i], bh, acc[i]);
                wmma::mma_sync(acc[i], ah[i], bl, acc[i]);
                wmma::mma_sync(acc[i], al[i], bh, acc[i]);
            }
        }
#pragma unroll
        for (int i = 0; i < 2; i++)
            wmma::store_matrix_sync(&sPart[(size_t)((w * 2 + i) * 16) * SPLD], acc[i], SPLD,
                                    wmma::mem_row_major);
        __syncthreads();

        float ssum = 0.f;
#pragma unroll
        for (int ww = 0; ww < 16; ww++)
            ssum += sPart[(size_t)(((ww * 2 + (bf >> 4)) * 16) + (bf & 15)) * SPLD + jf];
        float val = tanhf(ssum + xv);
        hcat[((size_t)t * 1536 + d * HID + j0 + jf) * 32 + bf] = val;
        __nv_bfloat16 hi, lo;
        bfsplit(val, hi, lo);
        hnH[(size_t)(j0 + jf) * 32 + bf] = hi;
        hnL[(size_t)(j0 + jf) * 32 + bf] = lo;

        __syncthreads();
        if (tid == 0) st_rel(&flags[jb * 32], (unsigned)(s + 1));
        if (tid < 48)
            while (ld_acq(&flags[tid * 32]) < (unsigned)(s + 1)) { }
        __syncthreads();
    }
}

// ---------------- transpose [t][c][b] -> [t*32+b][c], tf32-rounded ----------------
__global__ void transpose_cb(const float* __restrict__ src, float* __restrict__ dst)
{
    __shared__ float tile[32][33];
    int cg = blockIdx.x * 32, t = blockIdx.y, x = threadIdx.x;
    for (int y = threadIdx.y; y < 32; y += 8)
        tile[y][x] = src[((size_t)t * 1536 + cg + y) * 32 + x];
    __syncthreads();
    for (int y = threadIdx.y; y < 32; y += 8)
        dst[((size_t)t * 32 + y) * 1536 + cg + x] = tf32r(tile[x][y]);
}

// ---------------- BN stats ----------------
__global__ __launch_bounds__(256) void bn_stats(const float* __restrict__ hcat,
                                                float* __restrict__ mean,
                                                float* __restrict__ rstd)
{
    int t = blockIdx.x, tid = threadIdx.x;
    const float* p = hcat + (size_t)t * 49152;
    float s = 0.f, q = 0.f;
    for (int i = tid; i < 49152; i += 256) { float v = p[i]; s += v; q += v * v; }
    __shared__ float rs[256], rq[256];
    rs[tid] = s; rq[tid] = q;
    __syncthreads();
    for (int o = 128; o > 0; o >>= 1) {
        if (tid < o) { rs[tid] += rs[tid + o]; rq[tid] += rq[tid + o]; }
        __syncthreads();
    }
    if (tid == 0) {
        float m = rs[0] * (1.f / 49152.f);
        float v = rq[0] * (1.f / 49152.f) - m * m;
        mean[t] = m;
        rstd[t] = rsqrtf(v + 1e-5f);
    }
}

// ---------------- fused transpose + BN normalize -> bf16 hi/lo ----------------
__global__ void transpose_norm(const float* __restrict__ src,
                               __nv_bfloat16* __restrict__ dh, __nv_bfloat16* __restrict__ dl,
                               const float* __restrict__ mean, const float* __restrict__ rstd,
                               const float* __restrict__ gamma, const float* __restrict__ beta)
{
    __shared__ float tile[32][33];
    int cg = blockIdx.x * 32, t = blockIdx.y, x = threadIdx.x;
    float mu = mean[t];
    float sc = rstd[t] * gamma[t];
    float bb = beta[t];
    for (int y = threadIdx.y; y < 32; y += 8)
        tile[y][x] = src[((size_t)t * 1536 + cg + y) * 32 + x];
    __syncthreads();
    for (int y = threadIdx.y; y < 32; y += 8) {
        float v = (tile[x][y] - mu) * sc + bb;
        __nv_bfloat16 hi, lo;
        bfsplit(v, hi, lo);
        size_t idx = ((size_t)t * 32 + y) * 1536 + cg + x;
        dh[idx] = hi;
        dl[idx] = lo;
    }
}

// ---------------- launch ----------------
extern "C" void kernel_launch(void* const* d_in, const int* in_sizes, int n_in,
                              void* d_out, int out_size)
{
    const int*   tokens  = (const int*)d_in[0];
    const float* emb     = (const float*)d_in[1];
    const float* w_ih_l0 = (const float*)d_in[2];
    const float* w_hh_l0 = (const float*)d_in[3];
    const float* b_ih_l0 = (const float*)d_in[4];
    const float* b_hh_l0 = (const float*)d_in[5];
    const float* w_ih_l1 = (const float*)d_in[6];
    const float* w_hh_l1 = (const float*)d_in[7];
    const float* b_ih_l1 = (const float*)d_in[8];
    const float* b_hh_l1 = (const float*)d_in[9];
    const float* gamma   = (const float*)d_in[10];
    const float* beta    = (const float*)d_in[11];
    const float* lin_w   = (const float*)d_in[12];
    const float* lin_b   = (const float*)d_in[13];
    float* out = (float*)d_out;

    float *X, *xp, *hcat, *hmat, *mean, *rstd, *wih0, *wih1, *probe;
    __nv_bfloat16 *WpH, *WpL, *hmH, *hmL;
    cudaGetSymbolAddress((void**)&X,    g_X);
    cudaGetSymbolAddress((void**)&xp,   g_xp);
    cudaGetSymbolAddress((void**)&hcat, g_hcat);
    cudaGetSymbolAddress((void**)&hmat, g_hmat);
    cudaGetSymbolAddress((void**)&mean, g_mean);
    cudaGetSymbolAddress((void**)&rstd, g_rstd);
    cudaGetSymbolAddress((void**)&wih0, g_wih0);
    cudaGetSymbolAddress((void**)&wih1, g_wih1);
    cudaGetSymbolAddress((void**)&probe, g_probe);
    cudaGetSymbolAddress((void**)&WpH, g_WpH);
    cudaGetSymbolAddress((void**)&WpL, g_WpL);
    cudaGetSymbolAddress((void**)&hmH, g_hmH);
    cudaGetSymbolAddress((void**)&hmL, g_hmL);

    const int GEMM_SMEM = 2 * STGF * 4;                         // 81920 B
    const int BF_SMEM   = 2 * STGH * 2;                         // 81920 B
    const int RNN_SMEM  = 2 * 16 * 776 * 2 + 16 * 2 * 16 * SPLD * 4;
    cudaFuncSetAttribute(gemm2, cudaFuncAttributeMaxDynamicSharedMemorySize, GEMM_SMEM);
    cudaFuncSetAttribute(gemm3<0>, cudaFuncAttributeMaxDynamicSharedMemorySize, BF_SMEM);
    cudaFuncSetAttribute(gemm3<2>, cudaFuncAttributeMaxDynamicSharedMemorySize, BF_SMEM);
    cudaFuncSetAttribute(rnn_layer, cudaFuncAttributeMaxDynamicSharedMemorySize, RNN_SMEM);

    // 1) embed
    embed_kernel<<<8192, 128>>>(tokens, emb, X);
    // 2) split lin_w into bf16 hi/lo (padded)
    prep_wsplit<<<10240 * 384 / 256, 256>>>(lin_w, WpH, WpL);
    // 3) reset
    rnn_reset<<<96, 512>>>();
    // 4) PROBE at the captured slot: new projection GEMM, 148 CTAs = 1/SM, K=1536
    gemm3<2><<<dim3(37, 4), 512, BF_SMEM>>>(hmH, hmL, WpH, WpL, lin_b, probe, 1536, 10240);

    // 5-6) weight rounding (tf32, input GEMMs)
    prep_round<<<(2 * 768 * 512 / 4 + 255) / 256, 256>>>(w_ih_l0, wih0, 2 * 768 * 512 / 4);
    prep_round<<<(2 * 768 * 1536 / 4 + 255) / 256, 256>>>(w_ih_l1, wih1, 2 * 768 * 1536 / 4);

    // 7) layer 0 input GEMMs, K=512
    gemm2<<<dim3(6, 64, 2), 256, GEMM_SMEM>>>(
        X, wih0, b_ih_l0, b_hh_l0, xp, 512,
        (size_t)HID * 512, (size_t)L_SEQ * HID * 32, HID);

    // 8) layer 0 recurrence
    rnn_reset<<<96, 512>>>();
    rnn_layer<<<96, 512, RNN_SMEM>>>(xp, w_hh_l0, hcat, L_SEQ);

    // 9) transpose
    transpose_cb<<<dim3(48, 256), dim3(32, 8)>>>(hcat, hmat);

    // 10) layer 1 input GEMMs, K=1536
    gemm2<<<dim3(6, 64, 2), 256, GEMM_SMEM>>>(
        hmat, wih1, b_ih_l1, b_hh_l1, xp, 1536,
        (size_t)HID * 1536, (size_t)L_SEQ * HID * 32, HID);

    // 11) layer 1 recurrence
    rnn_reset<<<96, 512>>>();
    rnn_layer<<<96, 512, RNN_SMEM>>>(xp, w_hh_l1, hcat, L_SEQ);

    // 12) BN + normalize (bf16 split output)
    bn_stats<<<256, 256>>>(hcat, mean, rstd);
    transpose_norm<<<dim3(48, 256), dim3(32, 8)>>>(hcat, hmH, hmL, mean, rstd, gamma, beta);

    // 13) projection (bf16 3-term, v2)
    gemm3<0><<<dim3(80, 64), 512, BF_SMEM>>>(hmH, hmL, WpH, WpL, lin_b, out, 1536, 10000);
}

// round 17
// speedup vs baseline: 1.1808x; 1.1808x over previous
#include <cuda_runtime.h>
#include <mma.h>
#include <cuda_bf16.h>
#include <cstdint>
#include <cstdio>

using namespace nvcuda;

#define L_SEQ 256
#define HID 768

// ---------------- scratch ----------------
__device__ __nv_bfloat16 g_XH[8192u * 512];   // embedded input hi, row m = t*32+b
__device__ __nv_bfloat16 g_XL[8192u * 512];   // embedded input lo
__device__ float g_xp[2u * 256 * 768 * 32];   // xp[d][t][j][b]
__device__ __nv_bfloat16 g_hH[2][2][768][32]; // ping-pong h hi [pp][d][k][b] (k-major)
__device__ __nv_bfloat16 g_hL[2][2][768][32]; // ping-pong h lo
__device__ float g_hcat[256u * 1536 * 32];    // layer output [t][c][b]
__device__ __nv_bfloat16 g_WpH[10240u * 1536];  // projection weights hi (padded)
__device__ __nv_bfloat16 g_WpL[10240u * 1536];  // projection weights lo
__device__ __nv_bfloat16 g_hmH[8192u * 1536];   // [m][c] bf16 hi (l1 input, then proj input)
__device__ __nv_bfloat16 g_hmL[8192u * 1536];   // [m][c] bf16 lo
__device__ __nv_bfloat16 g_wih0H[2u * 768 * 512];
__device__ __nv_bfloat16 g_wih0L[2u * 768 * 512];
__device__ __nv_bfloat16 g_wih1H[2u * 768 * 1536];
__device__ __nv_bfloat16 g_wih1L[2u * 768 * 1536];
__device__ float g_mean[256];
__device__ float g_rstd[256];
__device__ unsigned g_flag[2][48 * 32];       // per-block step flags, 128B stride

// ---------------- helpers ----------------
__device__ __forceinline__ void cp_async16(void* sdst, const void* gsrc) {
    uint32_t sa = (uint32_t)__cvta_generic_to_shared(sdst);
    asm volatile("cp.async.cg.shared.global [%0], [%1], 16;\n" :: "r"(sa), "l"(gsrc));
}
__device__ __forceinline__ void cp_commit() { asm volatile("cp.async.commit_group;\n"); }
template<int N> __device__ __forceinline__ void cp_wait() {
    asm volatile("cp.async.wait_group %0;\n" :: "n"(N));
}
__device__ __forceinline__ unsigned ld_acq(const unsigned* p) {
    unsigned o;
    asm volatile("ld.acquire.gpu.global.u32 %0, [%1];" : "=r"(o) : "l"(p) : "memory");
    return o;
}
__device__ __forceinline__ void st_rel(unsigned* p, unsigned v) {
    asm volatile("st.release.gpu.global.u32 [%0], %1;" :: "l"(p), "r"(v) : "memory");
}
__device__ __forceinline__ void bfsplit(float v, __nv_bfloat16& hi, __nv_bfloat16& lo) {
    hi = __float2bfloat16(v);
    lo = __float2bfloat16(v - __bfloat162float(hi));
}

// ---------------- embedding gather -> bf16 hi/lo ----------------
__global__ void embed_kernel(const int* __restrict__ tokens,
                             const float* __restrict__ emb,
                             __nv_bfloat16* __restrict__ XH,
                             __nv_bfloat16* __restrict__ XL)
{
    int m = blockIdx.x, t = m >> 5, b = m & 31;
    int tok = tokens[b * L_SEQ + t];
    float4 v = ((const float4*)(emb + (size_t)tok * 512))[threadIdx.x];
    size_t base = (size_t)m * 512 + threadIdx.x * 4;
    float vv[4] = {v.x, v.y, v.z, v.w};
#pragma unroll
    for (int q = 0; q < 4; q++) {
        __nv_bfloat16 hi, lo;
        bfsplit(vv[q], hi, lo);
        XH[base + q] = hi;
        XL[base + q] = lo;
    }
}

// ---------------- weight split (fp32 -> bf16 hi/lo) ----------------
__global__ void prep_split(const float* __restrict__ src,
                           __nv_bfloat16* __restrict__ dh, __nv_bfloat16* __restrict__ dl,
                           int n4)
{
    int i = blockIdx.x * 256 + threadIdx.x;
    if (i < n4) {
        float4 v = ((const float4*)src)[i];
        float vv[4] = {v.x, v.y, v.z, v.w};
#pragma unroll
        for (int q = 0; q < 4; q++) {
            __nv_bfloat16 hi, lo;
            bfsplit(vv[q], hi, lo);
            dh[i * 4 + q] = hi;
            dl[i * 4 + q] = lo;
        }
    }
}
__global__ void prep_wsplit(const float* __restrict__ lw,
                            __nv_bfloat16* __restrict__ dh, __nv_bfloat16* __restrict__ dl)
{
    size_t i = (size_t)blockIdx.x * 256 + threadIdx.x;   // float4 idx, total 10240*384
    int row = (int)(i / 384);
    float4 v = make_float4(0.f, 0.f, 0.f, 0.f);
    if (row < 10000) v = ((const float4*)lw)[i];
    float vv[4] = {v.x, v.y, v.z, v.w};
#pragma unroll
    for (int q = 0; q < 4; q++) {
        __nv_bfloat16 hi, lo;
        bfsplit(vv[q], hi, lo);
        dh[i * 4 + q] = hi;
        dl[i * 4 + q] = lo;
    }
}

// ---------------- reset for persistent recurrence ----------------
__global__ void rnn_reset()
{
    int i = blockIdx.x * blockDim.x + threadIdx.x;   // 49152 threads
    __nv_bfloat16* hH0 = &g_hH[0][0][0][0];
    __nv_bfloat16* hL0 = &g_hL[0][0][0][0];
    hH0[i] = __float2bfloat16(0.f);
    hL0[i] = __float2bfloat16(0.f);
    if (i < 2 * 48 * 32) (&g_flag[0][0])[i] = 0u;
}

// ================= bf16 3-term GEMM (R15 shape: 256 thr, 64x32 warp tiles) ======
// C = A @ W^T with A,W pre-split bf16 hi/lo. acc += ah*wh + ah*wl + al*wh.
// MODE 0: projection out[(b*256+t)][n] + b1, guard n < Nout
// MODE 1: rnn layout C[(t*768+n)*32+b] + b1[n] + b2[n]   (z = direction)
#define GBM 128
#define GBN 128
#define GBK 32
#define GLD 40
#define HLD3 40            // smem ld in halfs
#define STGH 20480         // halfs per stage: 4 tiles * 128 * 40

template<int MODE>
__global__ __launch_bounds__(256, 2) void gemm3(
    const __nv_bfloat16* __restrict__ Ah, const __nv_bfloat16* __restrict__ Al,
    const __nv_bfloat16* __restrict__ Wh, const __nv_bfloat16* __restrict__ Wl,
    const float* __restrict__ b1, const float* __restrict__ b2,
    float* __restrict__ C, int K, int Nout,
    size_t wStride, size_t cStride, int bStride)
{
    extern __shared__ __align__(16) char smraw[];
    __nv_bfloat16* smh = (__nv_bfloat16*)smraw;

    int z = blockIdx.z;
    Wh += (size_t)z * wStride;
    Wl += (size_t)z * wStride;
    C  += (size_t)z * cStride;
    b1 += z * bStride;
    if (MODE == 1) b2 += z * bStride;

    int tid = threadIdx.x, warp = tid >> 5, lane = tid & 31;
    int wm = warp >> 2, wn = warp & 3;    // 2x4 grid, warp tile 64x32
    int m0 = blockIdx.y * GBM, n0 = blockIdx.x * GBN;
    int ntiles = K / GBK;

    auto loadtile = [&](int kt, int buf) {
        int k0 = kt * GBK;
        __nv_bfloat16* s = smh + (size_t)buf * STGH;
#pragma unroll
        for (int i = 0; i < 2; i++) {
            int ch = tid + i * 256, r = ch >> 2, cg = ch & 3;
            cp_async16(&s[r * HLD3 + cg * 8], Ah + (size_t)(m0 + r) * K + k0 + cg * 8);
        }
#pragma unroll
        for (int i = 0; i < 2; i++) {
            int ch = tid + i * 256, r = ch >> 2, cg = ch & 3;
            cp_async16(&s[5120 + r * HLD3 + cg * 8], Al + (size_t)(m0 + r) * K + k0 + cg * 8);
        }
#pragma unroll
        for (int i = 0; i < 2; i++) {
            int ch = tid + i * 256, r = ch >> 2, cg = ch & 3;
            cp_async16(&s[10240 + r * HLD3 + cg * 8], Wh + (size_t)(n0 + r) * K + k0 + cg * 8);
        }
#pragma unroll
        for (int i = 0; i < 2; i++) {
            int ch = tid + i * 256, r = ch >> 2, cg = ch & 3;
            cp_async16(&s[15360 + r * HLD3 + cg * 8], Wl + (size_t)(n0 + r) * K + k0 + cg * 8);
        }
    };

    wmma::fragment<wmma::accumulator, 16, 16, 16, float> acc[4][2];
#pragma unroll
    for (int i = 0; i < 4; i++)
#pragma unroll
        for (int j = 0; j < 2; j++) wmma::fill_fragment(acc[i][j], 0.0f);

    loadtile(0, 0);
    cp_commit();

    int buf = 0;
    for (int kt = 0; kt < ntiles; kt++) {
        cp_wait<0>();
        __syncthreads();
        if (kt + 1 < ntiles) { loadtile(kt + 1, buf ^ 1); cp_commit(); }

        const __nv_bfloat16* S = smh + (size_t)buf * STGH;
        const __nv_bfloat16* A0h = S + wm * 64 * HLD3;
        const __nv_bfloat16* A0l = S + 5120 + wm * 64 * HLD3;
        const __nv_bfloat16* B0h = S + 10240 + wn * 32 * HLD3;
        const __nv_bfloat16* B0l = S + 15360 + wn * 32 * HLD3;
#pragma unroll
        for (int kk = 0; kk < 2; kk++) {
            wmma::fragment<wmma::matrix_a, 16, 16, 16, __nv_bfloat16, wmma::row_major> ah[4], al[4];
            wmma::fragment<wmma::matrix_b, 16, 16, 16, __nv_bfloat16, wmma::col_major> bh[2], bl[2];
#pragma unroll
            for (int i = 0; i < 4; i++) {
                wmma::load_matrix_sync(ah[i], A0h + (size_t)i * 16 * HLD3 + kk * 16, HLD3);
                wmma::load_matrix_sync(al[i], A0l + (size_t)i * 16 * HLD3 + kk * 16, HLD3);
            }
#pragma unroll
            for (int j = 0; j < 2; j++) {
                wmma::load_matrix_sync(bh[j], B0h + (size_t)j * 16 * HLD3 + kk * 16, HLD3);
                wmma::load_matrix_sync(bl[j], B0l + (size_t)j * 16 * HLD3 + kk * 16, HLD3);
            }
#pragma unroll
            for (int i = 0; i < 4; i++)
#pragma unroll
                for (int j = 0; j < 2; j++) {
                    wmma::mma_sync(acc[i][j], ah[i], bh[j], acc[i][j]);
                    wmma::mma_sync(acc[i][j], ah[i], bl[j], acc[i][j]);
                    wmma::mma_sync(acc[i][j], al[i], bh[j], acc[i][j]);
                }
        }
        __syncthreads();
        buf ^= 1;
    }

    // epilogue: per-warp 64x40 float staging (8 warps * 64*40*4B = 81920 B)
    float* sC = (float*)smraw + (size_t)warp * 64 * GLD;
#pragma unroll
    for (int i = 0; i < 4; i++)
#pragma unroll
        for (int j = 0; j < 2; j++)
            wmma::store_matrix_sync(sC + (size_t)i * 16 * GLD + j * 16, acc[i][j], GLD,
                                    wmma::mem_row_major);
    __syncwarp();

    if (MODE == 0) {
        int n = n0 + wn * 32 + lane;
        if (n < Nout) {
            float bv = b1[n];
#pragma unroll 4
            for (int ml = 0; ml < 64; ml++) {
                int m = m0 + wm * 64 + ml;
                float v = sC[ml * GLD + lane] + bv;
                int row = (m & 31) * L_SEQ + (m >> 5);
                C[(size_t)row * Nout + n] = v;
            }
        }
    } else {
#pragma unroll
        for (int half = 0; half < 2; half++) {
            int ml = half * 32 + lane;
            int m = m0 + wm * 64 + ml;
            int t = m >> 5, b = m & 31;
#pragma unroll 4
            for (int nl = 0; nl < 32; nl++) {
                int n = n0 + wn * 32 + nl;
                float v = sC[ml * GLD + nl] + b1[n] + b2[n];
                C[((size_t)t * HID + n) * 32 + b] = v;
            }
        }
    }
}

// ================= persistent bi-RNN layer v6 (R15 verbatim) ====================
#define SPLD 20

__global__ __launch_bounds__(512, 1) void rnn_layer(
    const float* __restrict__ xp,
    const float* __restrict__ Whh,
    float* __restrict__ hcat,
    int nsteps)
{
    extern __shared__ __align__(16) char smraw[];
    __nv_bfloat16* sWh = (__nv_bfloat16*)smraw;                 // [16][776]
    __nv_bfloat16* sWl = sWh + 16 * 776;
    float* sPart = (float*)(smraw + 2 * 16 * 776 * 2);          // [16w][2i][16r][SPLD]

    int blk = blockIdx.x;
    int d = blk / 48, jb = blk % 48, j0 = jb * 16;
    int tid = threadIdx.x, w = tid >> 5;

    const float* Wd = Whh + (size_t)d * HID * HID;
    for (int i = tid; i < 16 * 192; i += 512) {
        int j = i / 192, c = i % 192;
        float4 v = *(const float4*)&Wd[(size_t)(j0 + j) * HID + c * 4];
        float vv[4] = {v.x, v.y, v.z, v.w};
#pragma unroll
        for (int q = 0; q < 4; q++) {
            __nv_bfloat16 hi, lo;
            bfsplit(vv[q], hi, lo);
            sWh[j * 776 + c * 4 + q] = hi;
            sWl[j * 776 + c * 4 + q] = lo;
        }
    }
    __syncthreads();

    const float* xpd = xp + (size_t)d * L_SEQ * HID * 32;
    int jf = tid >> 5, bf = tid & 31;
    unsigned* flags = &g_flag[d][0];

    for (int s = 0; s < nsteps; s++) {
        int t = d ? (L_SEQ - 1 - s) : s;
        const __nv_bfloat16* hpH = &g_hH[s & 1][d][0][0];
        const __nv_bfloat16* hpL = &g_hL[s & 1][d][0][0];
        __nv_bfloat16* hnH = &g_hH[(s + 1) & 1][d][0][0];
        __nv_bfloat16* hnL = &g_hL[(s + 1) & 1][d][0][0];

        float xv = xpd[((size_t)t * HID + j0 + jf) * 32 + bf];

        wmma::fragment<wmma::accumulator, 16, 16, 16, float> acc[2];
        wmma::fill_fragment(acc[0], 0.0f);
        wmma::fill_fragment(acc[1], 0.0f);

        int kbase = w * 48;
#pragma unroll
        for (int kt = 0; kt < 3; kt++) {
            int k = kbase + kt * 16;
            wmma::fragment<wmma::matrix_a, 16, 16, 16, __nv_bfloat16, wmma::col_major> ah[2], al[2];
#pragma unroll
            for (int i = 0; i < 2; i++) {
                wmma::load_matrix_sync(ah[i], hpH + (size_t)k * 32 + i * 16, 32);
                wmma::load_matrix_sync(al[i], hpL + (size_t)k * 32 + i * 16, 32);
            }
            wmma::fragment<wmma::matrix_b, 16, 16, 16, __nv_bfloat16, wmma::col_major> bh, bl;
            wmma::load_matrix_sync(bh, sWh + k, 776);
            wmma::load_matrix_sync(bl, sWl + k, 776);
#pragma unroll
            for (int i = 0; i < 2; i++) {
                wmma::mma_sync(acc[i], ah[i], bh, acc[i]);
                wmma::mma_sync(acc[i], ah[i], bl, acc[i]);
                wmma::mma_sync(acc[i], al[i], bh, acc[i]);
            }
        }
#pragma unroll
        for (int i = 0; i < 2; i++)
            wmma::store_matrix_sync(&sPart[(size_t)((w * 2 + i) * 16) * SPLD], acc[i], SPLD,
                                    wmma::mem_row_major);
        __syncthreads();

        float ssum = 0.f;
#pragma unroll
        for (int ww = 0; ww < 16; ww++)
            ssum += sPart[(size_t)(((ww * 2 + (bf >> 4)) * 16) + (bf & 15)) * SPLD + jf];
        float val = tanhf(ssum + xv);
        hcat[((size_t)t * 1536 + d * HID + j0 + jf) * 32 + bf] = val;
        __nv_bfloat16 hi, lo;
        bfsplit(val, hi, lo);
        hnH[(size_t)(j0 + jf) * 32 + bf] = hi;
        hnL[(size_t)(j0 + jf) * 32 + bf] = lo;

        __syncthreads();
        if (tid == 0) st_rel(&flags[jb * 32], (unsigned)(s + 1));
        if (tid < 48)
            while (ld_acq(&flags[tid * 32]) < (unsigned)(s + 1)) { }
        __syncthreads();
    }
}

// ---------------- transpose [t][c][b] -> [t*32+b][c] bf16 hi/lo ----------------
__global__ void transpose_cb(const float* __restrict__ src,
                             __nv_bfloat16* __restrict__ dh, __nv_bfloat16* __restrict__ dl)
{
    __shared__ float tile[32][33];
    int cg = blockIdx.x * 32, t = blockIdx.y, x = threadIdx.x;
    for (int y = threadIdx.y; y < 32; y += 8)
        tile[y][x] = src[((size_t)t * 1536 + cg + y) * 32 + x];
    __syncthreads();
    for (int y = threadIdx.y; y < 32; y += 8) {
        __nv_bfloat16 hi, lo;
        bfsplit(tile[x][y], hi, lo);
        size_t idx = ((size_t)t * 32 + y) * 1536 + cg + x;
        dh[idx] = hi;
        dl[idx] = lo;
    }
}

// ---------------- BN stats ----------------
__global__ __launch_bounds__(256) void bn_stats(const float* __restrict__ hcat,
                                                float* __restrict__ mean,
                                                float* __restrict__ rstd)
{
    int t = blockIdx.x, tid = threadIdx.x;
    const float* p = hcat + (size_t)t * 49152;
    float s = 0.f, q = 0.f;
    for (int i = tid; i < 49152; i += 256) { float v = p[i]; s += v; q += v * v; }
    __shared__ float rs[256], rq[256];
    rs[tid] = s; rq[tid] = q;
    __syncthreads();
    for (int o = 128; o > 0; o >>= 1) {
        if (tid < o) { rs[tid] += rs[tid + o]; rq[tid] += rq[tid + o]; }
        __syncthreads();
    }
    if (tid == 0) {
        float m = rs[0] * (1.f / 49152.f);
        float v = rq[0] * (1.f / 49152.f) - m * m;
        mean[t] = m;
        rstd[t] = rsqrtf(v + 1e-5f);
    }
}

// ---------------- fused transpose + BN normalize -> bf16 hi/lo ----------------
__global__ void transpose_norm(const float* __restrict__ src,
                               __nv_bfloat16* __restrict__ dh, __nv_bfloat16* __restrict__ dl,
                               const float* __restrict__ mean, const float* __restrict__ rstd,
                               const float* __restrict__ gamma, const float* __restrict__ beta)
{
    __shared__ float tile[32][33];
    int cg = blockIdx.x * 32, t = blockIdx.y, x = threadIdx.x;
    float mu = mean[t];
    float sc = rstd[t] * gamma[t];
    float bb = beta[t];
    for (int y = threadIdx.y; y < 32; y += 8)
        tile[y][x] = src[((size_t)t * 1536 + cg + y) * 32 + x];
    __syncthreads();
    for (int y = threadIdx.y; y < 32; y += 8) {
        float v = (tile[x][y] - mu) * sc + bb;
        __nv_bfloat16 hi, lo;
        bfsplit(v, hi, lo);
        size_t idx = ((size_t)t * 32 + y) * 1536 + cg + x;
        dh[idx] = hi;
        dl[idx] = lo;
    }
}

// ---------------- launch ----------------
extern "C" void kernel_launch(void* const* d_in, const int* in_sizes, int n_in,
                              void* d_out, int out_size)
{
    const int*   tokens  = (const int*)d_in[0];
    const float* emb     = (const float*)d_in[1];
    const float* w_ih_l0 = (const float*)d_in[2];
    const float* w_hh_l0 = (const float*)d_in[3];
    const float* b_ih_l0 = (const float*)d_in[4];
    const float* b_hh_l0 = (const float*)d_in[5];
    const float* w_ih_l1 = (const float*)d_in[6];
    const float* w_hh_l1 = (const float*)d_in[7];
    const float* b_ih_l1 = (const float*)d_in[8];
    const float* b_hh_l1 = (const float*)d_in[9];
    const float* gamma   = (const float*)d_in[10];
    const float* beta    = (const float*)d_in[11];
    const float* lin_w   = (const float*)d_in[12];
    const float* lin_b   = (const float*)d_in[13];
    float* out = (float*)d_out;

    float *xp, *hcat, *mean, *rstd;
    __nv_bfloat16 *XH, *XL, *WpH, *WpL, *hmH, *hmL, *w0H, *w0L, *w1H, *w1L;
    cudaGetSymbolAddress((void**)&xp,   g_xp);
    cudaGetSymbolAddress((void**)&hcat, g_hcat);
    cudaGetSymbolAddress((void**)&mean, g_mean);
    cudaGetSymbolAddress((void**)&rstd, g_rstd);
    cudaGetSymbolAddress((void**)&XH,  g_XH);
    cudaGetSymbolAddress((void**)&XL,  g_XL);
    cudaGetSymbolAddress((void**)&WpH, g_WpH);
    cudaGetSymbolAddress((void**)&WpL, g_WpL);
    cudaGetSymbolAddress((void**)&hmH, g_hmH);
    cudaGetSymbolAddress((void**)&hmL, g_hmL);
    cudaGetSymbolAddress((void**)&w0H, g_wih0H);
    cudaGetSymbolAddress((void**)&w0L, g_wih0L);
    cudaGetSymbolAddress((void**)&w1H, g_wih1H);
    cudaGetSymbolAddress((void**)&w1L, g_wih1L);

    const int BF_SMEM  = 2 * STGH * 2;                          // 81920 B -> 2 CTA/SM
    const int RNN_SMEM = 2 * 16 * 776 * 2 + 16 * 2 * 16 * SPLD * 4;
    cudaFuncSetAttribute(gemm3<0>, cudaFuncAttributeMaxDynamicSharedMemorySize, BF_SMEM);
    cudaFuncSetAttribute(gemm3<1>, cudaFuncAttributeMaxDynamicSharedMemorySize, BF_SMEM);
    cudaFuncSetAttribute(rnn_layer, cudaFuncAttributeMaxDynamicSharedMemorySize, RNN_SMEM);

    // 1) embed -> bf16 hi/lo
    embed_kernel<<<8192, 128>>>(tokens, emb, XH, XL);
    // 2) weight splits
    prep_wsplit<<<10240 * 384 / 256, 256>>>(lin_w, WpH, WpL);
    prep_split<<<(2 * 768 * 512 / 4 + 255) / 256, 256>>>(w_ih_l0, w0H, w0L, 2 * 768 * 512 / 4);
    prep_split<<<(2 * 768 * 1536 / 4 + 255) / 256, 256>>>(w_ih_l1, w1H, w1L, 2 * 768 * 1536 / 4);

    // 3) layer 0 input GEMMs (bf16 3-term, rnn layout), K=512
    gemm3<1><<<dim3(6, 64, 2), 256, BF_SMEM>>>(
        XH, XL, w0H, w0L, b_ih_l0, b_hh_l0, xp, 512, HID,
        (size_t)HID * 512, (size_t)L_SEQ * HID * 32, HID);

    // 4) layer 0 recurrence
    rnn_reset<<<96, 512>>>();
    rnn_layer<<<96, 512, RNN_SMEM>>>(xp, w_hh_l0, hcat, L_SEQ);

    // 5) transpose -> bf16 hi/lo (l1 input reuses hm buffers)
    transpose_cb<<<dim3(48, 256), dim3(32, 8)>>>(hcat, hmH, hmL);

    // 6) layer 1 input GEMMs, K=1536
    gemm3<1><<<dim3(6, 64, 2), 256, BF_SMEM>>>(
        hmH, hmL, w1H, w1L, b_ih_l1, b_hh_l1, xp, 1536, HID,
        (size_t)HID * 1536, (size_t)L_SEQ * HID * 32, HID);

    // 7) layer 1 recurrence
    rnn_reset<<<96, 512>>>();
    rnn_layer<<<96, 512, RNN_SMEM>>>(xp, w_hh_l1, hcat, L_SEQ);

    // 8) BN + normalize (bf16 split output, overwrites hm buffers)
    bn_stats<<<256, 256>>>(hcat, mean, rstd);
    transpose_norm<<<dim3(48, 256), dim3(32, 8)>>>(hcat, hmH, hmL, mean, rstd, gamma, beta);

    // 9) projection (bf16 3-term, R15 shape)
    gemm3<0><<<dim3(80, 64, 1), 256, BF_SMEM>>>(
        hmH, hmL, WpH, WpL, lin_b, nullptr, out, 1536, 10000, 0, 0, 0);
}